// round 16
// baseline (speedup 1.0000x reference)
#include <cuda_runtime.h>
#include <cuda_fp16.h>
#include <mma.h>
#include <cstdint>

using namespace nvcuda;

#define B_  512
#define T_  512
#define I_  128
#define H_  512
#define C_  128
#define OT_ 128

// persistent kernel: grid 16x8 = 128 CTAs = 16 clusters of 8 (cluster = one mx group)
#define GX    16
#define GY    8
#define NT    256
#define LDA   648         // unified K layout: h cols 0-511, x cols 512-639 (+8 pad)
#define LDC3  68          // padded f32 leading dim for 64-wide C slabs
#define SLAB  2176        // one sC slab: 32*68 floats

// fc kernels: CTA 64x32, 4 warps, KC 64
#define KC   64
#define LD   72
#define LDC  36

// ---------------- device globals (allocation-free scratch) ----------------
__device__ __half g_x16[(size_t)B_ * T_ * I_];
__device__ __half g_Whh16[H_ * H_];
__device__ __half g_Wih16[H_ * I_];
__device__ __half g_f116[H_ * H_];
__device__ __half g_f216[C_ * H_];
__device__ __half g_h0h[B_ * H_], g_h1h[B_ * H_];   // single-plane hidden, ping-pong
__device__ __half g_nhh[(size_t)OT_ * B_ * H_];     // decoder nh hi
__device__ __half g_nhl[(size_t)OT_ * B_ * H_];     // decoder nh lo (fc precision)
__device__ __half g_mh[(size_t)OT_ * B_ * H_];      // fc1 out hi
__device__ __half g_ml[(size_t)OT_ * B_ * H_];      // fc1 out lo
__device__ float  g_bias2[H_];                      // b_ih + b_hh
__device__ int    g_len64;

// ---------------- prologue kernels ----------------
__global__ void convh_kernel(const float* __restrict__ s, __half* __restrict__ d, long n4) {
    long i = (long)blockIdx.x * blockDim.x + threadIdx.x;
    if (i >= n4) return;
    float4 v = reinterpret_cast<const float4*>(s)[i];
    union { __half b[4]; uint2 u; } h;
    h.b[0] = __float2half_rn(v.x); h.b[1] = __float2half_rn(v.y);
    h.b[2] = __float2half_rn(v.z); h.b[3] = __float2half_rn(v.w);
    reinterpret_cast<uint2*>(d)[i] = h.u;
}

__global__ void init_kernel(const float* __restrict__ b_ih, const float* __restrict__ b_hh) {
    int i = blockIdx.x * blockDim.x + threadIdx.x;
    if (i < H_) g_bias2[i] = b_ih[i] + b_hh[i];
    if (i < B_ * H_) g_h0h[i] = __float2half(0.f);
}

// lengths dtype sniff: int64 buffers have all odd int32 words == 0 (values < 512)
__global__ void detect_len_kernel(const int* p) {
    int is64 = 1;
    for (int i = 0; i < 32; i++)
        if (p[2 * i + 1] != 0) is64 = 0;
    g_len64 = is64;
}

// ---------------- cluster barrier (release-arrive / acquire-wait) ----------------
#define CLUSTER_SYNC_() do {                                           \
    asm volatile("barrier.cluster.arrive.aligned;" ::: "memory");      \
    asm volatile("barrier.cluster.wait.aligned;"   ::: "memory");      \
} while (0)

#define CP16(dst_u32, src_ptr) \
    asm volatile("cp.async.cg.shared.global [%0], [%1], 16;" \
                 :: "r"(dst_u32), "l"(src_ptr) : "memory")
#define CP_COMMIT()  asm volatile("cp.async.commit_group;" ::: "memory")
#define CP_WAIT0()   asm volatile("cp.async.wait_group 0;" ::: "memory")

__device__ __forceinline__ float tanh_fast(float x) {
    float y;
    asm("tanh.approx.f32 %0, %1;" : "=f"(y) : "f"(x));
    return y;
}

// ---------------- persistent serial-chain kernel ----------------
// SMEM (bytes), CTA tile 32x64:
//   sW : [64][648] half = 82944   (cols 0-511: Whh, 512-639: Wih, unified K)
//   sA : [32][648] half = 41472   (cols 0-511: h,   512-639: x_t)
//   sC : 4 K-quarter slabs x [32][68] f32 = 34816
#define SW_OFF 0
#define SA_OFF 82944
#define SC_OFF 124416
#define SMEM_PERS 159232

__global__ void __launch_bounds__(NT, 1) __cluster_dims__(1, GY, 1)
rnn_persistent(const __half* __restrict__ x16, const void* __restrict__ lengths)
{
    extern __shared__ __align__(16) char smem[];
    __half* sW = reinterpret_cast<__half*>(smem + SW_OFF);
    __half* sA = reinterpret_cast<__half*>(smem + SA_OFF);
    float*  sC = reinterpret_cast<float*>(smem + SC_OFF);

    uint32_t saA;
    asm("{ .reg .u64 t; cvta.to.shared.u64 t, %1; cvt.u32.u64 %0, t; }" : "=r"(saA) : "l"(sA));

    const int tid = threadIdx.x;
    const int wid = tid >> 5;
    const int wm  = wid & 1;        // m-frag row: 16*wm
    const int wk  = wid >> 1;       // K-quarter: 0..3
    const int m0  = blockIdx.x * 32;
    const int n0  = blockIdx.y * 64;

    // ---- resident weight tile (loaded once): 64 n-rows, unified K cols ----
#pragma unroll
    for (int i = 0; i < 16; i++) {                   // Whh: 64 x 512 -> cols 0-511
        int id = tid + i * NT; int r = id >> 6, c = id & 63;
        *reinterpret_cast<uint4*>(sW + r * LDA + c * 8) =
            *reinterpret_cast<const uint4*>(g_Whh16 + (size_t)(n0 + r) * H_ + c * 8);
    }
#pragma unroll
    for (int i = 0; i < 4; i++) {                    // Wih: 64 x 128 -> cols 512-639
        int id = tid + i * NT; int r = id >> 4, c = id & 15;
        *reinterpret_cast<uint4*>(sW + r * LDA + 512 + c * 8) =
            *reinterpret_cast<const uint4*>(g_Wih16 + (size_t)(n0 + r) * I_ + c * 8);
    }

    // epilogue constants: thread -> (row er of 32, 8-col group of 64)
    const int er  = tid >> 3;
    const int ec0 = (tid & 7) * 8;
    const int em  = m0 + er;
    const int enb = n0 + ec0;
    float biasr[8];
#pragma unroll
    for (int j = 0; j < 8; j++) biasr[j] = g_bias2[enb + j];
    const long long mylen = g_len64 ? ((const long long*)lengths)[em]
                                    : (long long)((const int*)lengths)[em];
    __syncthreads();

    // x prefetch for step t (2 granules/thread into sA cols 512-639)
    auto prefetch_x = [&](int t) {
#pragma unroll
        for (int i = 0; i < 2; i++) {
            int id = tid + i * NT; int r = id >> 4, c = id & 15;
            CP16(saA + (uint32_t)(r * LDA + 512 + c * 8) * 2,
                 x16 + (size_t)(m0 + r) * (T_ * I_) + (size_t)t * I_ + c * 8);
        }
        CP_COMMIT();
    };

    // one step's GEMM; x for this step (if any) was prefetched by the PREVIOUS step.
    // px = next step's x to prefetch (-1 = none), issued after sA is fully consumed.
    auto run_gemm = [&](const __half* __restrict__ Asrc, int nks, int px) {
        // h rows: 8 granules/thread, then wait for h AND previously-prefetched x
#pragma unroll
        for (int i = 0; i < 8; i++) {
            int id = tid + i * NT; int r = id >> 6, c = id & 63;
            CP16(saA + (uint32_t)(r * LDA + c * 8) * 2,
                 Asrc + (size_t)(m0 + r) * H_ + c * 8);
        }
        CP_COMMIT();
        CP_WAIT0();
        __syncthreads();

        wmma::fragment<wmma::accumulator, 16, 16, 16, float> acc[4];
#pragma unroll
        for (int nf = 0; nf < 4; nf++) wmma::fill_fragment(acc[nf], 0.f);

        const int kcnt = nks >> 2;
        const int ks0  = wk * kcnt;
        const __half* aB = sA + (wm * 16) * LDA;
#pragma unroll 2
        for (int ks = ks0; ks < ks0 + kcnt; ks++) {
            const int kk = ks * 16;
            wmma::fragment<wmma::matrix_a, 16, 16, 16, __half, wmma::row_major> a;
            wmma::fragment<wmma::matrix_b, 16, 16, 16, __half, wmma::col_major> b0, b1, b2, b3;
            wmma::load_matrix_sync(a,  aB + kk, LDA);
            wmma::load_matrix_sync(b0, sW + kk,            LDA);
            wmma::load_matrix_sync(b1, sW + 16 * LDA + kk, LDA);
            wmma::load_matrix_sync(b2, sW + 32 * LDA + kk, LDA);
            wmma::load_matrix_sync(b3, sW + 48 * LDA + kk, LDA);
            wmma::mma_sync(acc[0], a, b0, acc[0]);
            wmma::mma_sync(acc[1], a, b1, acc[1]);
            wmma::mma_sync(acc[2], a, b2, acc[2]);
            wmma::mma_sync(acc[3], a, b3, acc[3]);
        }
        float* slab = sC + wk * SLAB + (wm * 16) * LDC3;
#pragma unroll
        for (int nf = 0; nf < 4; nf++)
            wmma::store_matrix_sync(slab + nf * 16, acc[nf], LDC3, wmma::mem_row_major);
        __syncthreads();
        if (px >= 0) prefetch_x(px);   // overlaps epilogue + cluster barrier
    };

    auto fold = [&](float* v) {
#pragma unroll
        for (int j = 0; j < 8; j++) v[j] = 0.f;
#pragma unroll
        for (int w = 0; w < 4; w++) {
            const float* p = sC + w * SLAB + er * LDC3 + ec0;
            float4 u0 = *reinterpret_cast<const float4*>(p);
            float4 u1 = *reinterpret_cast<const float4*>(p + 4);
            v[0] += u0.x; v[1] += u0.y; v[2] += u0.z; v[3] += u0.w;
            v[4] += u1.x; v[5] += u1.y; v[6] += u1.z; v[7] += u1.w;
        }
    };

    union P { __half b[8]; uint4 u; };
    P hprev; hprev.u = make_uint4(0u, 0u, 0u, 0u);   // h0 = 0; frozen-row register cache

    prefetch_x(0);   // x_0 in flight before the first step

    // ---- encoder: 512 serial steps (x @ Wih fused via unified K cols 512-639) ----
    for (int t = 0; t < T_; t++) {
        const __half* Ah = (t & 1) ? g_h1h : g_h0h;
        __half*       Oh = (t & 1) ? g_h0h : g_h1h;
        run_gemm(Ah, 40, (t + 1 < T_) ? t + 1 : -1);

        float v[8];
        fold(v);
        if ((long long)t < mylen) {
#pragma unroll
            for (int j = 0; j < 8; j++)
                hprev.b[j] = __float2half_rn(tanh_fast(v[j] + biasr[j]));
        }
        *reinterpret_cast<uint4*>(Oh + (size_t)em * H_ + enb) = hprev.u;
        CLUSTER_SYNC_();
    }

    // ---- decoder h-chain: 128 serial steps into nh slab (final h in g_h0h) ----
    const size_t BH = (size_t)B_ * H_;
    for (int s = 0; s < OT_; s++) {
        const __half* Ah = (s == 0) ? g_h0h : g_nhh + (size_t)(s - 1) * BH;
        run_gemm(Ah, 32, -1);

        float v[8];
        fold(v);
        P ph, pl;
#pragma unroll
        for (int j = 0; j < 8; j++) {
            float z = tanh_fast(v[j] + biasr[j]);
            __half hb = __float2half_rn(z);
            ph.b[j] = hb;
            pl.b[j] = __float2half_rn(z - __half2float(hb));   // lo plane for fc precision
        }
        *reinterpret_cast<uint4*>(g_nhh + (size_t)s * BH + (size_t)em * H_ + enb) = ph.u;
        *reinterpret_cast<uint4*>(g_nhl + (size_t)s * BH + (size_t)em * H_ + enb) = pl.u;
        CLUSTER_SYNC_();
    }
}

// ---------------- batched FC kernels (parallel; A 2-plane, W fp16) ----------------
// MODE 0: fc1: out = relu(A@fc1W^T + b) -> half hi/lo slab
// MODE 1: fc2: out[b][s][:] = A@fc2W^T + b -> fp32 strided (slab row m -> s = m>>9, b = m&511)
template <int MODE>
__global__ void __launch_bounds__(128)
fc_kernel(const __half* __restrict__ Ah, const __half* __restrict__ Al,
          const __half* __restrict__ Bw,
          const float* __restrict__ bias,
          __half* __restrict__ outh, __half* __restrict__ outl,
          float* __restrict__ outf)
{
    __shared__ __align__(16) char smem[23040];
    __half* sAh = reinterpret_cast<__half*>(smem);            // 9216 B
    __half* sAl = reinterpret_cast<__half*>(smem + 9216);     // 9216 B
    __half* sB  = reinterpret_cast<__half*>(smem + 18432);    // 4608 B
    float*  sC  = reinterpret_cast<float*>(smem);             // reuse after mma

    const int tid = threadIdx.x, wid = tid >> 5;
    const int wy = wid >> 1, wx = wid & 1;
    const int m0 = blockIdx.x * 64;
    const int n0 = blockIdx.y * 32;

    wmma::fragment<wmma::accumulator, 16, 16, 16, float> acc00, acc01, acc10, acc11;
    wmma::fill_fragment(acc00, 0.f);
    wmma::fill_fragment(acc01, 0.f);
    wmma::fill_fragment(acc10, 0.f);
    wmma::fill_fragment(acc11, 0.f);

    uint4 raH[4], raL[4], rb[2];
    auto prefetch = [&](int c) {
        const int k0 = c * KC;
#pragma unroll
        for (int i = 0; i < 4; i++) {
            int id = tid + i * 128; int r = id >> 3, cc = id & 7;
            size_t g = (size_t)(m0 + r) * H_ + k0 + cc * 8;
            raH[i] = *reinterpret_cast<const uint4*>(Ah + g);
            raL[i] = *reinterpret_cast<const uint4*>(Al + g);
        }
#pragma unroll
        for (int i = 0; i < 2; i++) {
            int id = tid + i * 128; int r = id >> 3, cc = id & 7;
            rb[i] = *reinterpret_cast<const uint4*>(Bw + (size_t)(n0 + r) * H_ + k0 + cc * 8);
        }
    };
    auto stores = [&]() {
#pragma unroll
        for (int i = 0; i < 4; i++) {
            int id = tid + i * 128; int r = id >> 3, cc = id & 7;
            *reinterpret_cast<uint4*>(sAh + r * LD + cc * 8) = raH[i];
            *reinterpret_cast<uint4*>(sAl + r * LD + cc * 8) = raL[i];
        }
#pragma unroll
        for (int i = 0; i < 2; i++) {
            int id = tid + i * 128; int r = id >> 3, cc = id & 7;
            *reinterpret_cast<uint4*>(sB + r * LD + cc * 8) = rb[i];
        }
    };

    prefetch(0);
    for (int s = 0; s < H_ / KC; s++) {
        stores();
        __syncthreads();
        if (s + 1 < H_ / KC) prefetch(s + 1);
#pragma unroll
        for (int ks = 0; ks < 4; ks++) {
            const int kk = ks * 16;
            wmma::fragment<wmma::matrix_a, 16, 16, 16, __half, wmma::row_major> aH0, aH1, aL0, aL1;
            wmma::fragment<wmma::matrix_b, 16, 16, 16, __half, wmma::col_major> b;
            wmma::load_matrix_sync(aH0, sAh + (wy * 32)      * LD + kk, LD);
            wmma::load_matrix_sync(aH1, sAh + (wy * 32 + 16) * LD + kk, LD);
            wmma::load_matrix_sync(aL0, sAl + (wy * 32)      * LD + kk, LD);
            wmma::load_matrix_sync(aL1, sAl + (wy * 32 + 16) * LD + kk, LD);
            wmma::load_matrix_sync(b,   sB  + (wx * 16) * LD + kk, LD);
            wmma::mma_sync(acc00, aH0, b, acc00);
            wmma::mma_sync(acc10, aH1, b, acc10);
            wmma::mma_sync(acc01, aL0, b, acc01);
            wmma::mma_sync(acc11, aL1, b, acc11);
        }
        __syncthreads();
    }

#pragma unroll
    for (int e = 0; e < acc00.num_elements; e++) {
        acc00.x[e] += acc01.x[e];
        acc10.x[e] += acc11.x[e];
    }
    wmma::store_matrix_sync(sC + (wy * 32)      * LDC + wx * 16, acc00, LDC, wmma::mem_row_major);
    wmma::store_matrix_sync(sC + (wy * 32 + 16) * LDC + wx * 16, acc10, LDC, wmma::mem_row_major);
    __syncthreads();

    const int r  = tid >> 1;
    const int c0 = (tid & 1) * 16;
    const int m  = m0 + r;
    const int nb = n0 + c0;

    float v[16];
#pragma unroll
    for (int j = 0; j < 4; j++)
        *reinterpret_cast<float4*>(v + j * 4) =
            *reinterpret_cast<const float4*>(sC + r * LDC + c0 + j * 4);

    if constexpr (MODE == 0) {
        union P8 { __half b[8]; uint4 u; } ph[2], pl[2];
#pragma unroll
        for (int j = 0; j < 16; j++) {
            float z = fmaxf(v[j] + bias[nb + j], 0.f);
            __half hb = __float2half_rn(z);
            ph[j >> 3].b[j & 7] = hb;
            pl[j >> 3].b[j & 7] = __float2half_rn(z - __half2float(hb));
        }
        __half* oh = outh + (size_t)m * H_ + nb;
        __half* ol = outl + (size_t)m * H_ + nb;
        reinterpret_cast<uint4*>(oh)[0] = ph[0].u; reinterpret_cast<uint4*>(oh)[1] = ph[1].u;
        reinterpret_cast<uint4*>(ol)[0] = pl[0].u; reinterpret_cast<uint4*>(ol)[1] = pl[1].u;
    } else {
        const int s = m >> 9;
        const int b = m & 511;
        float* op = outf + ((size_t)b * OT_ + s) * C_ + nb;
#pragma unroll
        for (int j = 0; j < 16; j++) v[j] += bias[nb + j];
#pragma unroll
        for (int j = 0; j < 4; j++)
            *reinterpret_cast<float4*>(op + j * 4) = *reinterpret_cast<const float4*>(v + j * 4);
    }
}

// ---------------- host ----------------
extern "C" void kernel_launch(void* const* d_in, const int* in_sizes, int n_in,
                              void* d_out, int out_size) {
    const float* x       = (const float*)d_in[0];
    const void*  lengths = d_in[1];
    const float* W_ih = (const float*)d_in[3];
    const float* W_hh = (const float*)d_in[4];
    const float* b_ih = (const float*)d_in[5];
    const float* b_hh = (const float*)d_in[6];
    const float* fc1W = (const float*)d_in[7];
    const float* fc1b = (const float*)d_in[8];
    const float* fc2W = (const float*)d_in[9];
    const float* fc2b = (const float*)d_in[10];
    float* out = (float*)d_out;

    __half *x16, *Whh16, *Wih16, *f116, *f216, *nhh, *nhl, *mh, *ml;
    cudaGetSymbolAddress((void**)&x16,   g_x16);
    cudaGetSymbolAddress((void**)&Whh16, g_Whh16); cudaGetSymbolAddress((void**)&Wih16, g_Wih16);
    cudaGetSymbolAddress((void**)&f116,  g_f116);  cudaGetSymbolAddress((void**)&f216,  g_f216);
    cudaGetSymbolAddress((void**)&nhh,   g_nhh);   cudaGetSymbolAddress((void**)&nhl,   g_nhl);
    cudaGetSymbolAddress((void**)&mh,    g_mh);    cudaGetSymbolAddress((void**)&ml,    g_ml);

    // prologue: fp16 conversions; bias2; h0 = 0; lengths dtype
    long nx4 = (long)B_ * T_ * I_ / 4;
    convh_kernel<<<(unsigned)((nx4 + 255) / 256), 256>>>(x, x16, nx4);
    convh_kernel<<<(H_ * H_ / 4 + 255) / 256, 256>>>(W_hh, Whh16, H_ * H_ / 4);
    convh_kernel<<<(H_ * I_ / 4 + 255) / 256, 256>>>(W_ih, Wih16, H_ * I_ / 4);
    convh_kernel<<<(H_ * H_ / 4 + 255) / 256, 256>>>(fc1W, f116, H_ * H_ / 4);
    convh_kernel<<<(C_ * H_ / 4 + 255) / 256, 256>>>(fc2W, f216, C_ * H_ / 4);
    init_kernel<<<(B_ * H_ + 255) / 256, 256>>>(b_ih, b_hh);
    detect_len_kernel<<<1, 1>>>((const int*)lengths);

    // whole serial chain in ONE persistent kernel (16 independent clusters of 8)
    cudaFuncSetAttribute(rnn_persistent, cudaFuncAttributeMaxDynamicSharedMemorySize, SMEM_PERS);
    rnn_persistent<<<dim3(GX, GY), NT, SMEM_PERS>>>(x16, lengths);

    // batched fc1 / fc2 over all (s, b): M = OT*B = 65536
    fc_kernel<0><<<dim3(OT_ * B_ / 64, H_ / 32), 128>>>(nhh, nhl, f116, fc1b, mh, ml, nullptr);
    fc_kernel<1><<<dim3(OT_ * B_ / 64, C_ / 32), 128>>>(mh, ml, f216, fc2b, nullptr, nullptr, out);
}

// round 17
// speedup vs baseline: 1.3580x; 1.3580x over previous
#include <cuda_runtime.h>
#include <cuda_fp16.h>
#include <mma.h>
#include <cstdint>

using namespace nvcuda;

#define B_  512
#define T_  512
#define I_  128
#define H_  512
#define C_  128
#define OT_ 128

// persistent kernel: grid 16x8 = 128 CTAs, CTA tile 32x64, 8 warps = 2 m-frags x 4 K-quarters
#define GX    16
#define GY    8
#define NGRP  8           // CTAs per sync group (one group per mx)
#define NT    256
#define LDA   648         // unified K layout: h cols 0-511, x cols 512-639 (+8 pad)
#define LDC3  68          // padded f32 leading dim for 64-wide C slabs
#define SLAB  2176        // one sC slab: 32*68 floats

// fc kernels: CTA 64x32, 4 warps, KC 64
#define KC   64
#define LD   72
#define LDC  36

// ---------------- device globals (allocation-free scratch) ----------------
__device__ __half g_x16[(size_t)B_ * T_ * I_];
__device__ __half g_Whh16[H_ * H_];
__device__ __half g_Wih16[H_ * I_];
__device__ __half g_f116[H_ * H_];
__device__ __half g_f216[C_ * H_];
__device__ __half g_h0h[B_ * H_], g_h1h[B_ * H_];   // single-plane hidden, ping-pong
__device__ __half g_nhh[(size_t)OT_ * B_ * H_];     // decoder nh hi
__device__ __half g_nhl[(size_t)OT_ * B_ * H_];     // decoder nh lo (fc precision)
__device__ __half g_mh[(size_t)OT_ * B_ * H_];      // fc1 out hi
__device__ __half g_ml[(size_t)OT_ * B_ * H_];      // fc1 out lo
__device__ float  g_bias2[H_];                      // b_ih + b_hh
__device__ int    g_len64;
// per-CTA step flags, each on its own 128B line: index (grp*NGRP + ny) * 32
__device__ volatile unsigned g_flag[GX * NGRP * 32];

// ---------------- prologue kernels ----------------
__global__ void convh_kernel(const float* __restrict__ s, __half* __restrict__ d, long n4) {
    long i = (long)blockIdx.x * blockDim.x + threadIdx.x;
    if (i >= n4) return;
    float4 v = reinterpret_cast<const float4*>(s)[i];
    union { __half b[4]; uint2 u; } h;
    h.b[0] = __float2half_rn(v.x); h.b[1] = __float2half_rn(v.y);
    h.b[2] = __float2half_rn(v.z); h.b[3] = __float2half_rn(v.w);
    reinterpret_cast<uint2*>(d)[i] = h.u;
}

__global__ void init_kernel(const float* __restrict__ b_ih, const float* __restrict__ b_hh) {
    int i = blockIdx.x * blockDim.x + threadIdx.x;
    if (i < H_) g_bias2[i] = b_ih[i] + b_hh[i];
    if (i < B_ * H_) g_h0h[i] = __float2half(0.f);
    if (i < GX * NGRP * 32) g_flag[i] = 0u;
}

// lengths dtype sniff: int64 buffers have all odd int32 words == 0 (values < 512)
__global__ void detect_len_kernel(const int* p) {
    int is64 = 1;
    for (int i = 0; i < 32; i++)
        if (p[2 * i + 1] != 0) is64 = 0;
    g_len64 = is64;
}

// ---------------- distributed-flag group barrier (8 CTAs sharing one mx) ----------------
// arrive: own-flag store (no contention); wait: threads 0-7 poll distinct peers' flags.
__device__ __forceinline__ void group_sync(int grp, int myj, unsigned& gen) {
    __syncthreads();                 // all threads' h STGs issued
    gen++;
    if (threadIdx.x == 0) {
        __threadfence();             // release: h writes visible before flag
        g_flag[(grp * NGRP + myj) * 32] = gen;
    }
    if (threadIdx.x < NGRP) {
        while (g_flag[(grp * NGRP + threadIdx.x) * 32] < gen) __nanosleep(32);
        __threadfence();             // acquire: peers' h visible to subsequent reads
    }
    __syncthreads();
}

#define CP16(dst_u32, src_ptr) \
    asm volatile("cp.async.cg.shared.global [%0], [%1], 16;" \
                 :: "r"(dst_u32), "l"(src_ptr) : "memory")
#define CP_COMMIT()  asm volatile("cp.async.commit_group;" ::: "memory")
#define CP_WAIT0()   asm volatile("cp.async.wait_group 0;" ::: "memory")

__device__ __forceinline__ float tanh_fast(float x) {
    float y;
    asm("tanh.approx.f32 %0, %1;" : "=f"(y) : "f"(x));
    return y;
}

// ---------------- persistent serial-chain kernel ----------------
// SMEM (bytes), CTA tile 32x64:
//   sW : [64][648] half = 82944   (cols 0-511: Whh, 512-639: Wih, unified K)
//   sA : [32][648] half = 41472   (cols 0-511: h,   512-639: x_t)
//   sC : 4 K-quarter slabs x [32][68] f32 = 34816
#define SW_OFF 0
#define SA_OFF 82944
#define SC_OFF 124416
#define SMEM_PERS 159232

__global__ void __launch_bounds__(NT, 1) rnn_persistent(
    const __half* __restrict__ x16, const void* __restrict__ lengths)
{
    extern __shared__ __align__(16) char smem[];
    __half* sW = reinterpret_cast<__half*>(smem + SW_OFF);
    __half* sA = reinterpret_cast<__half*>(smem + SA_OFF);
    float*  sC = reinterpret_cast<float*>(smem + SC_OFF);

    uint32_t saA;
    asm("{ .reg .u64 t; cvta.to.shared.u64 t, %1; cvt.u32.u64 %0, t; }" : "=r"(saA) : "l"(sA));

    const int tid = threadIdx.x;
    const int wid = tid >> 5;
    const int wm  = wid & 1;        // m-frag row: 16*wm
    const int wk  = wid >> 1;       // K-quarter: 0..3
    const int m0  = blockIdx.x * 32;
    const int n0  = blockIdx.y * 64;
    const int grp = blockIdx.x;
    const int myj = blockIdx.y;

    // ---- resident weight tile (loaded once): 64 n-rows, unified K cols ----
#pragma unroll
    for (int i = 0; i < 16; i++) {                   // Whh: 64 x 512 -> cols 0-511
        int id = tid + i * NT; int r = id >> 6, c = id & 63;
        *reinterpret_cast<uint4*>(sW + r * LDA + c * 8) =
            *reinterpret_cast<const uint4*>(g_Whh16 + (size_t)(n0 + r) * H_ + c * 8);
    }
#pragma unroll
    for (int i = 0; i < 4; i++) {                    // Wih: 64 x 128 -> cols 512-639
        int id = tid + i * NT; int r = id >> 4, c = id & 15;
        *reinterpret_cast<uint4*>(sW + r * LDA + 512 + c * 8) =
            *reinterpret_cast<const uint4*>(g_Wih16 + (size_t)(n0 + r) * I_ + c * 8);
    }

    // epilogue constants: thread -> (row er of 32, 8-col group of 64)
    const int er  = tid >> 3;
    const int ec0 = (tid & 7) * 8;
    const int em  = m0 + er;
    const int enb = n0 + ec0;
    float biasr[8];
#pragma unroll
    for (int j = 0; j < 8; j++) biasr[j] = g_bias2[enb + j];
    const long long mylen = g_len64 ? ((const long long*)lengths)[em]
                                    : (long long)((const int*)lengths)[em];
    __syncthreads();

    unsigned gen = 0;

    // x prefetch for step t (2 granules/thread into sA cols 512-639)
    auto prefetch_x = [&](int t) {
#pragma unroll
        for (int i = 0; i < 2; i++) {
            int id = tid + i * NT; int r = id >> 4, c = id & 15;
            CP16(saA + (uint32_t)(r * LDA + 512 + c * 8) * 2,
                 x16 + (size_t)(m0 + r) * (T_ * I_) + (size_t)t * I_ + c * 8);
        }
        CP_COMMIT();
    };

    // one step's GEMM; x for this step (if any) was prefetched by the PREVIOUS step.
    // px = next step's x to prefetch (-1 = none), issued after sA is fully consumed.
    auto run_gemm = [&](const __half* __restrict__ Asrc, int nks, int px) {
        // h rows: 8 granules/thread, then wait for h AND previously-prefetched x
#pragma unroll
        for (int i = 0; i < 8; i++) {
            int id = tid + i * NT; int r = id >> 6, c = id & 63;
            CP16(saA + (uint32_t)(r * LDA + c * 8) * 2,
                 Asrc + (size_t)(m0 + r) * H_ + c * 8);
        }
        CP_COMMIT();
        CP_WAIT0();
        __syncthreads();

        wmma::fragment<wmma::accumulator, 16, 16, 16, float> acc[4];
#pragma unroll
        for (int nf = 0; nf < 4; nf++) wmma::fill_fragment(acc[nf], 0.f);

        const int kcnt = nks >> 2;
        const int ks0  = wk * kcnt;
        const __half* aB = sA + (wm * 16) * LDA;
#pragma unroll 2
        for (int ks = ks0; ks < ks0 + kcnt; ks++) {
            const int kk = ks * 16;
            wmma::fragment<wmma::matrix_a, 16, 16, 16, __half, wmma::row_major> a;
            wmma::fragment<wmma::matrix_b, 16, 16, 16, __half, wmma::col_major> b0, b1, b2, b3;
            wmma::load_matrix_sync(a,  aB + kk, LDA);
            wmma::load_matrix_sync(b0, sW + kk,            LDA);
            wmma::load_matrix_sync(b1, sW + 16 * LDA + kk, LDA);
            wmma::load_matrix_sync(b2, sW + 32 * LDA + kk, LDA);
            wmma::load_matrix_sync(b3, sW + 48 * LDA + kk, LDA);
            wmma::mma_sync(acc[0], a, b0, acc[0]);
            wmma::mma_sync(acc[1], a, b1, acc[1]);
            wmma::mma_sync(acc[2], a, b2, acc[2]);
            wmma::mma_sync(acc[3], a, b3, acc[3]);
        }
        float* slab = sC + wk * SLAB + (wm * 16) * LDC3;
#pragma unroll
        for (int nf = 0; nf < 4; nf++)
            wmma::store_matrix_sync(slab + nf * 16, acc[nf], LDC3, wmma::mem_row_major);
        __syncthreads();
        if (px >= 0) prefetch_x(px);   // overlaps epilogue + group barrier
    };

    auto fold = [&](float* v) {
#pragma unroll
        for (int j = 0; j < 8; j++) v[j] = 0.f;
#pragma unroll
        for (int w = 0; w < 4; w++) {
            const float* p = sC + w * SLAB + er * LDC3 + ec0;
            float4 u0 = *reinterpret_cast<const float4*>(p);
            float4 u1 = *reinterpret_cast<const float4*>(p + 4);
            v[0] += u0.x; v[1] += u0.y; v[2] += u0.z; v[3] += u0.w;
            v[4] += u1.x; v[5] += u1.y; v[6] += u1.z; v[7] += u1.w;
        }
    };

    union P { __half b[8]; uint4 u; };
    P hprev; hprev.u = make_uint4(0u, 0u, 0u, 0u);   // h0 = 0; frozen-row register cache

    prefetch_x(0);   // x_0 in flight before the first step

    // ---- encoder: 512 serial steps (x @ Wih fused via unified K cols 512-639) ----
    for (int t = 0; t < T_; t++) {
        const __half* Ah = (t & 1) ? g_h1h : g_h0h;
        __half*       Oh = (t & 1) ? g_h0h : g_h1h;
        run_gemm(Ah, 40, (t + 1 < T_) ? t + 1 : -1);

        float v[8];
        fold(v);
        if ((long long)t < mylen) {
#pragma unroll
            for (int j = 0; j < 8; j++)
                hprev.b[j] = __float2half_rn(tanh_fast(v[j] + biasr[j]));
        }
        *reinterpret_cast<uint4*>(Oh + (size_t)em * H_ + enb) = hprev.u;
        group_sync(grp, myj, gen);
    }

    // ---- decoder h-chain: 128 serial steps into nh slab (final h in g_h0h) ----
    const size_t BH = (size_t)B_ * H_;
    for (int s = 0; s < OT_; s++) {
        const __half* Ah = (s == 0) ? g_h0h : g_nhh + (size_t)(s - 1) * BH;
        run_gemm(Ah, 32, -1);

        float v[8];
        fold(v);
        P ph, pl;
#pragma unroll
        for (int j = 0; j < 8; j++) {
            float z = tanh_fast(v[j] + biasr[j]);
            __half hb = __float2half_rn(z);
            ph.b[j] = hb;
            pl.b[j] = __float2half_rn(z - __half2float(hb));   // lo plane for fc precision
        }
        *reinterpret_cast<uint4*>(g_nhh + (size_t)s * BH + (size_t)em * H_ + enb) = ph.u;
        *reinterpret_cast<uint4*>(g_nhl + (size_t)s * BH + (size_t)em * H_ + enb) = pl.u;
        group_sync(grp, myj, gen);
    }
}

// ---------------- batched FC kernels (parallel; A 2-plane, W fp16) ----------------
// MODE 0: fc1: out = relu(A@fc1W^T + b) -> half hi/lo slab
// MODE 1: fc2: out[b][s][:] = A@fc2W^T + b -> fp32 strided (slab row m -> s = m>>9, b = m&511)
template <int MODE>
__global__ void __launch_bounds__(128)
fc_kernel(const __half* __restrict__ Ah, const __half* __restrict__ Al,
          const __half* __restrict__ Bw,
          const float* __restrict__ bias,
          __half* __restrict__ outh, __half* __restrict__ outl,
          float* __restrict__ outf)
{
    __shared__ __align__(16) char smem[23040];
    __half* sAh = reinterpret_cast<__half*>(smem);            // 9216 B
    __half* sAl = reinterpret_cast<__half*>(smem + 9216);     // 9216 B
    __half* sB  = reinterpret_cast<__half*>(smem + 18432);    // 4608 B
    float*  sC  = reinterpret_cast<float*>(smem);             // reuse after mma

    const int tid = threadIdx.x, wid = tid >> 5;
    const int wy = wid >> 1, wx = wid & 1;
    const int m0 = blockIdx.x * 64;
    const int n0 = blockIdx.y * 32;

    wmma::fragment<wmma::accumulator, 16, 16, 16, float> acc00, acc01, acc10, acc11;
    wmma::fill_fragment(acc00, 0.f);
    wmma::fill_fragment(acc01, 0.f);
    wmma::fill_fragment(acc10, 0.f);
    wmma::fill_fragment(acc11, 0.f);

    uint4 raH[4], raL[4], rb[2];
    auto prefetch = [&](int c) {
        const int k0 = c * KC;
#pragma unroll
        for (int i = 0; i < 4; i++) {
            int id = tid + i * 128; int r = id >> 3, cc = id & 7;
            size_t g = (size_t)(m0 + r) * H_ + k0 + cc * 8;
            raH[i] = *reinterpret_cast<const uint4*>(Ah + g);
            raL[i] = *reinterpret_cast<const uint4*>(Al + g);
        }
#pragma unroll
        for (int i = 0; i < 2; i++) {
            int id = tid + i * 128; int r = id >> 3, cc = id & 7;
            rb[i] = *reinterpret_cast<const uint4*>(Bw + (size_t)(n0 + r) * H_ + k0 + cc * 8);
        }
    };
    auto stores = [&]() {
#pragma unroll
        for (int i = 0; i < 4; i++) {
            int id = tid + i * 128; int r = id >> 3, cc = id & 7;
            *reinterpret_cast<uint4*>(sAh + r * LD + cc * 8) = raH[i];
            *reinterpret_cast<uint4*>(sAl + r * LD + cc * 8) = raL[i];
        }
#pragma unroll
        for (int i = 0; i < 2; i++) {
            int id = tid + i * 128; int r = id >> 3, cc = id & 7;
            *reinterpret_cast<uint4*>(sB + r * LD + cc * 8) = rb[i];
        }
    };

    prefetch(0);
    for (int s = 0; s < H_ / KC; s++) {
        stores();
        __syncthreads();
        if (s + 1 < H_ / KC) prefetch(s + 1);
#pragma unroll
        for (int ks = 0; ks < 4; ks++) {
            const int kk = ks * 16;
            wmma::fragment<wmma::matrix_a, 16, 16, 16, __half, wmma::row_major> aH0, aH1, aL0, aL1;
            wmma::fragment<wmma::matrix_b, 16, 16, 16, __half, wmma::col_major> b;
            wmma::load_matrix_sync(aH0, sAh + (wy * 32)      * LD + kk, LD);
            wmma::load_matrix_sync(aH1, sAh + (wy * 32 + 16) * LD + kk, LD);
            wmma::load_matrix_sync(aL0, sAl + (wy * 32)      * LD + kk, LD);
            wmma::load_matrix_sync(aL1, sAl + (wy * 32 + 16) * LD + kk, LD);
            wmma::load_matrix_sync(b,   sB  + (wx * 16) * LD + kk, LD);
            wmma::mma_sync(acc00, aH0, b, acc00);
            wmma::mma_sync(acc10, aH1, b, acc10);
            wmma::mma_sync(acc01, aL0, b, acc01);
            wmma::mma_sync(acc11, aL1, b, acc11);
        }
        __syncthreads();
    }

#pragma unroll
    for (int e = 0; e < acc00.num_elements; e++) {
        acc00.x[e] += acc01.x[e];
        acc10.x[e] += acc11.x[e];
    }
    wmma::store_matrix_sync(sC + (wy * 32)      * LDC + wx * 16, acc00, LDC, wmma::mem_row_major);
    wmma::store_matrix_sync(sC + (wy * 32 + 16) * LDC + wx * 16, acc10, LDC, wmma::mem_row_major);
    __syncthreads();

    const int r  = tid >> 1;
    const int c0 = (tid & 1) * 16;
    const int m  = m0 + r;
    const int nb = n0 + c0;

    float v[16];
#pragma unroll
    for (int j = 0; j < 4; j++)
        *reinterpret_cast<float4*>(v + j * 4) =
            *reinterpret_cast<const float4*>(sC + r * LDC + c0 + j * 4);

    if constexpr (MODE == 0) {
        union P8 { __half b[8]; uint4 u; } ph[2], pl[2];
#pragma unroll
        for (int j = 0; j < 16; j++) {
            float z = fmaxf(v[j] + bias[nb + j], 0.f);
            __half hb = __float2half_rn(z);
            ph[j >> 3].b[j & 7] = hb;
            pl[j >> 3].b[j & 7] = __float2half_rn(z - __half2float(hb));
        }
        __half* oh = outh + (size_t)m * H_ + nb;
        __half* ol = outl + (size_t)m * H_ + nb;
        reinterpret_cast<uint4*>(oh)[0] = ph[0].u; reinterpret_cast<uint4*>(oh)[1] = ph[1].u;
        reinterpret_cast<uint4*>(ol)[0] = pl[0].u; reinterpret_cast<uint4*>(ol)[1] = pl[1].u;
    } else {
        const int s = m >> 9;
        const int b = m & 511;
        float* op = outf + ((size_t)b * OT_ + s) * C_ + nb;
#pragma unroll
        for (int j = 0; j < 16; j++) v[j] += bias[nb + j];
#pragma unroll
        for (int j = 0; j < 4; j++)
            *reinterpret_cast<float4*>(op + j * 4) = *reinterpret_cast<const float4*>(v + j * 4);
    }
}

// ---------------- host ----------------
extern "C" void kernel_launch(void* const* d_in, const int* in_sizes, int n_in,
                              void* d_out, int out_size) {
    const float* x       = (const float*)d_in[0];
    const void*  lengths = d_in[1];
    const float* W_ih = (const float*)d_in[3];
    const float* W_hh = (const float*)d_in[4];
    const float* b_ih = (const float*)d_in[5];
    const float* b_hh = (const float*)d_in[6];
    const float* fc1W = (const float*)d_in[7];
    const float* fc1b = (const float*)d_in[8];
    const float* fc2W = (const float*)d_in[9];
    const float* fc2b = (const float*)d_in[10];
    float* out = (float*)d_out;

    __half *x16, *Whh16, *Wih16, *f116, *f216, *nhh, *nhl, *mh, *ml;
    cudaGetSymbolAddress((void**)&x16,   g_x16);
    cudaGetSymbolAddress((void**)&Whh16, g_Whh16); cudaGetSymbolAddress((void**)&Wih16, g_Wih16);
    cudaGetSymbolAddress((void**)&f116,  g_f116);  cudaGetSymbolAddress((void**)&f216,  g_f216);
    cudaGetSymbolAddress((void**)&nhh,   g_nhh);   cudaGetSymbolAddress((void**)&nhl,   g_nhl);
    cudaGetSymbolAddress((void**)&mh,    g_mh);    cudaGetSymbolAddress((void**)&ml,    g_ml);

    // prologue: fp16 conversions; bias2; h0 = 0; flags reset; lengths dtype
    long nx4 = (long)B_ * T_ * I_ / 4;
    convh_kernel<<<(unsigned)((nx4 + 255) / 256), 256>>>(x, x16, nx4);
    convh_kernel<<<(H_ * H_ / 4 + 255) / 256, 256>>>(W_hh, Whh16, H_ * H_ / 4);
    convh_kernel<<<(H_ * I_ / 4 + 255) / 256, 256>>>(W_ih, Wih16, H_ * I_ / 4);
    convh_kernel<<<(H_ * H_ / 4 + 255) / 256, 256>>>(fc1W, f116, H_ * H_ / 4);
    convh_kernel<<<(C_ * H_ / 4 + 255) / 256, 256>>>(fc2W, f216, C_ * H_ / 4);
    init_kernel<<<(B_ * H_ + 255) / 256, 256>>>(b_ih, b_hh);
    detect_len_kernel<<<1, 1>>>((const int*)lengths);

    // whole serial chain in ONE persistent kernel (16 independent 8-CTA groups)
    cudaFuncSetAttribute(rnn_persistent, cudaFuncAttributeMaxDynamicSharedMemorySize, SMEM_PERS);
    rnn_persistent<<<dim3(GX, GY), NT, SMEM_PERS>>>(x16, lengths);

    // batched fc1 / fc2 over all (s, b): M = OT*B = 65536
    fc_kernel<0><<<dim3(OT_ * B_ / 64, H_ / 32), 128>>>(nhh, nhl, f116, fc1b, mh, ml, nullptr);
    fc_kernel<1><<<dim3(OT_ * B_ / 64, C_ / 32), 128>>>(mh, ml, f216, fc2b, nullptr, nullptr, out);
}